// round 1
// baseline (speedup 1.0000x reference)
#include <cuda_runtime.h>
#include <math.h>

// NT-Xent loss, B=4096, D=128, T=0.5.
// sim = zn @ zn^T * (1/T); rowsum_i = sum_j exp(sim_ij) (incl. diagonal);
// lse_i = log(rowsum_i - e^2);  loss = (sum lse - 2*(1/T)*sum_i dot(zi_i,zj_i)) / 8192.

#define B_ROWS 4096
#define N_ROWS 8192
#define DVEC   128

static constexpr float INV_T = 2.0f;                 // 1/T
static constexpr float E2    = 7.38905609893065f;    // exp(2) = exp(sim_ii/T)

// scratch (no cudaMalloc allowed)
__device__ float g_zn[N_ROWS * DVEC];   // normalized rows (fp32), 4 MB
__device__ float g_rowsum[N_ROWS];      // sum_j exp(2*dot)
__device__ float g_pos[B_ROWS];         // dot(zn_i, zn_{i+B})

// ---------------------------------------------------------------- zero rowsum
__global__ void k_zero() {
    int i = blockIdx.x * blockDim.x + threadIdx.x;
    if (i < N_ROWS) g_rowsum[i] = 0.0f;
}

// ---------------------------------------------------------------- normalize
// one warp per row; lane holds 4 contiguous floats
__global__ void k_normalize(const float* __restrict__ zi,
                            const float* __restrict__ zj) {
    int warp = (blockIdx.x * blockDim.x + threadIdx.x) >> 5;
    int lane = threadIdx.x & 31;
    if (warp >= N_ROWS) return;
    const float* src = (warp < B_ROWS) ? (zi + (size_t)warp * DVEC)
                                       : (zj + (size_t)(warp - B_ROWS) * DVEC);
    float4 v = ((const float4*)src)[lane];
    float ss = v.x * v.x + v.y * v.y + v.z * v.z + v.w * v.w;
    #pragma unroll
    for (int o = 16; o > 0; o >>= 1) ss += __shfl_xor_sync(0xffffffffu, ss, o);
    float scale = 1.0f / fmaxf(sqrtf(ss), 1e-12f);
    v.x *= scale; v.y *= scale; v.z *= scale; v.w *= scale;
    ((float4*)(g_zn + (size_t)warp * DVEC))[lane] = v;
}

// ---------------------------------------------------------------- positive dots
// one warp per i in [0,B): dot(zn_i, zn_{i+B})
__global__ void k_pos() {
    int warp = (blockIdx.x * blockDim.x + threadIdx.x) >> 5;
    int lane = threadIdx.x & 31;
    if (warp >= B_ROWS) return;
    float4 a = ((const float4*)(g_zn + (size_t)warp * DVEC))[lane];
    float4 b = ((const float4*)(g_zn + (size_t)(warp + B_ROWS) * DVEC))[lane];
    float d = a.x * b.x + a.y * b.y + a.z * b.z + a.w * b.w;
    #pragma unroll
    for (int o = 16; o > 0; o >>= 1) d += __shfl_xor_sync(0xffffffffu, d, o);
    if (lane == 0) g_pos[warp] = d;
}

// ---------------------------------------------------------------- fused GEMM + exp + rowsum
// CTA tile: 64 rows x 64 cols per inner tile, 16 tiles (1024 cols) per CTA.
// grid = (128 rowblocks, 8 colsplits). Thread tile 4x4, threads 16x16.
// SMEM: As[64][129], Bs[64][129] fp32 (pad 1 float -> stride 129, odd mod 8,
// so the tx-strided b-loads hit 8 distinct bank groups: <=2-way conflict).
#define SM_PITCH 129
#define SMEM_MAIN (2 * 64 * SM_PITCH * 4)

__global__ void __launch_bounds__(256, 1) k_main() {
    extern __shared__ float sm[];
    float* As = sm;                   // [64][129]
    float* Bs = sm + 64 * SM_PITCH;   // [64][129]

    const int tid = threadIdx.x;
    const int tx  = tid & 15;         // col group
    const int ty  = tid >> 4;         // row group
    const int row0 = blockIdx.x * 64;
    const int col0 = blockIdx.y * 1024;

    // load A block (64 rows x 128) — coalesced float4, scalar STS
    #pragma unroll
    for (int i = 0; i < 8; i++) {
        int f  = tid + i * 256;
        int r  = f >> 5;              // 32 float4 per row
        int k4 = (f & 31) << 2;
        float4 v = *(const float4*)(g_zn + (size_t)(row0 + r) * DVEC + k4);
        As[r * SM_PITCH + k4 + 0] = v.x;
        As[r * SM_PITCH + k4 + 1] = v.y;
        As[r * SM_PITCH + k4 + 2] = v.z;
        As[r * SM_PITCH + k4 + 3] = v.w;
    }

    float rsum[4] = {0.0f, 0.0f, 0.0f, 0.0f};

    for (int t = 0; t < 16; t++) {
        __syncthreads();   // prior-iter readers done (also orders A fill on t=0 w/ next sync)
        int cbase = col0 + t * 64;
        #pragma unroll
        for (int i = 0; i < 8; i++) {
            int f  = tid + i * 256;
            int r  = f >> 5;
            int k4 = (f & 31) << 2;
            float4 v = *(const float4*)(g_zn + (size_t)(cbase + r) * DVEC + k4);
            Bs[r * SM_PITCH + k4 + 0] = v.x;
            Bs[r * SM_PITCH + k4 + 1] = v.y;
            Bs[r * SM_PITCH + k4 + 2] = v.z;
            Bs[r * SM_PITCH + k4 + 3] = v.w;
        }
        __syncthreads();

        float acc[4][4];
        #pragma unroll
        for (int r = 0; r < 4; r++)
            #pragma unroll
            for (int c = 0; c < 4; c++) acc[r][c] = 0.0f;

        #pragma unroll 4
        for (int k = 0; k < 128; k++) {
            float a[4], b[4];
            #pragma unroll
            for (int r = 0; r < 4; r++) a[r] = As[(ty * 4 + r) * SM_PITCH + k];
            #pragma unroll
            for (int c = 0; c < 4; c++) b[c] = Bs[(tx * 4 + c) * SM_PITCH + k];
            #pragma unroll
            for (int r = 0; r < 4; r++)
                #pragma unroll
                for (int c = 0; c < 4; c++) acc[r][c] = fmaf(a[r], b[c], acc[r][c]);
        }

        // epilogue: exp(2*dot), accumulate per-row (diagonal kept; subtracted later)
        #pragma unroll
        for (int r = 0; r < 4; r++) {
            float s = 0.0f;
            #pragma unroll
            for (int c = 0; c < 4; c++) s += __expf(INV_T * acc[r][c]);
            rsum[r] += s;
        }
    }

    // reduce across tx (16 lanes sharing a ty inside each warp), one atomic per row
    #pragma unroll
    for (int r = 0; r < 4; r++) {
        float v = rsum[r];
        #pragma unroll
        for (int o = 1; o < 16; o <<= 1) v += __shfl_xor_sync(0xffffffffu, v, o);
        if (tx == 0) atomicAdd(&g_rowsum[row0 + ty * 4 + r], v);
    }
}

// ---------------------------------------------------------------- finalize
__global__ void k_final(float* __restrict__ out) {
    __shared__ float red[256];
    int tid = threadIdx.x;
    float lsum = 0.0f;
    for (int i = tid; i < N_ROWS; i += 256)
        lsum += logf(g_rowsum[i] - E2);
    float psum = 0.0f;
    for (int i = tid; i < B_ROWS; i += 256)
        psum += g_pos[i];
    // sum over rows of pos-logit = 2 * INV_T * sum(dot)
    red[tid] = lsum - 2.0f * INV_T * psum;
    __syncthreads();
    for (int s = 128; s > 0; s >>= 1) {
        if (tid < s) red[tid] += red[tid + s];
        __syncthreads();
    }
    if (tid == 0) out[0] = red[0] / (float)N_ROWS;
}

// ---------------------------------------------------------------- launch
extern "C" void kernel_launch(void* const* d_in, const int* in_sizes, int n_in,
                              void* d_out, int out_size) {
    const float* zi = (const float*)d_in[0];
    const float* zj = (const float*)d_in[1];
    float* out = (float*)d_out;

    cudaFuncSetAttribute(k_main, cudaFuncAttributeMaxDynamicSharedMemorySize,
                         SMEM_MAIN);

    k_zero<<<(N_ROWS + 255) / 256, 256>>>();
    k_normalize<<<N_ROWS / 8, 256>>>(zi, zj);   // 8 warps/block, 1 row/warp
    k_pos<<<B_ROWS / 8, 256>>>();
    k_main<<<dim3(128, 8), 256, SMEM_MAIN>>>();
    k_final<<<1, 256>>>(out);
}

// round 3
// speedup vs baseline: 6.6604x; 6.6604x over previous
#include <cuda_runtime.h>
#include <cuda_bf16.h>
#include <math.h>
#include <stdint.h>

// NT-Xent loss, B=4096, D=128, T=0.5.
// rowsum_i = sum_j exp(2*dot(zn_i,zn_j)) (incl diagonal, subtracted as e^2),
// loss = (sum_i log(rowsum_i - e^2) - 4*sum_{i<B} pos_dot_i) / 8192.

#define B_ROWS 4096
#define N_ROWS 8192
#define DVEC   128

static constexpr float INV_T = 2.0f;
static constexpr float E2    = 7.38905609893065f;   // exp(2) = diagonal term
static constexpr float EPS_N = 1e-12f;

// scratch (no cudaMalloc allowed)
__device__ __nv_bfloat16 g_zb[N_ROWS * DVEC];   // normalized rows, bf16 (2 MB, L2-resident)
__device__ float g_rowsum[N_ROWS];
__device__ float g_pos[B_ROWS];

// ---------------------------------------------------------------- helpers
__device__ __forceinline__ uint32_t smem_u32(const void* p) {
    uint32_t a;
    asm("{ .reg .u64 t; cvta.to.shared.u64 t, %1; cvt.u32.u64 %0, t; }" : "=r"(a) : "l"(p));
    return a;
}

#define LDSM4(r, addr) \
    asm volatile("ldmatrix.sync.aligned.m8n8.x4.shared.b16 {%0,%1,%2,%3}, [%4];" \
                 : "=r"((r)[0]), "=r"((r)[1]), "=r"((r)[2]), "=r"((r)[3]) : "r"(addr))

#define MMA_BF16(d, a, b0, b1) \
    asm volatile("mma.sync.aligned.m16n8k16.row.col.f32.bf16.bf16.f32 " \
                 "{%0,%1,%2,%3}, {%4,%5,%6,%7}, {%8,%9}, {%0,%1,%2,%3};" \
                 : "+f"((d)[0]), "+f"((d)[1]), "+f"((d)[2]), "+f"((d)[3]) \
                 : "r"((a)[0]), "r"((a)[1]), "r"((a)[2]), "r"((a)[3]), \
                   "r"(b0), "r"(b1))

// exp(2*d) via range-reduced 2^y polynomial: fma pipe only, no MUFU.
__device__ __forceinline__ float exp2d(float d) {
    float y = d * 2.8853900817779268f;         // 2/ln2
    float r = y + 12582912.0f;                 // round-to-nearest (magic 1.5*2^23)
    int   kb = __float_as_int(r) << 23;        // k<<23 (signed-correct for small k)
    float f = y - (r - 12582912.0f);           // f in [-0.5, 0.5]
    float p = fmaf(0.0013333558f, f, 0.0096181291f);
    p = fmaf(p, f, 0.0555041087f);
    p = fmaf(p, f, 0.2402265070f);
    p = fmaf(p, f, 0.6931471806f);
    p = fmaf(p, f, 1.0f);
    return __int_as_float(__float_as_int(p) + kb);
}

// ---------------------------------------------------------------- small kernels
__global__ void k_zero() {
    int i = blockIdx.x * blockDim.x + threadIdx.x;
    if (i < N_ROWS) g_rowsum[i] = 0.0f;
}

// one warp per row: fp32 normalize -> bf16 store
__global__ void k_norm(const float* __restrict__ zi, const float* __restrict__ zj) {
    int warp = (blockIdx.x * blockDim.x + threadIdx.x) >> 5;
    int lane = threadIdx.x & 31;
    if (warp >= N_ROWS) return;
    const float* src = (warp < B_ROWS) ? (zi + (size_t)warp * DVEC)
                                       : (zj + (size_t)(warp - B_ROWS) * DVEC);
    float4 v = ((const float4*)src)[lane];
    float ss = v.x * v.x + v.y * v.y + v.z * v.z + v.w * v.w;
    #pragma unroll
    for (int o = 16; o > 0; o >>= 1) ss += __shfl_xor_sync(0xffffffffu, ss, o);
    float scale = 1.0f / fmaxf(sqrtf(ss), EPS_N);
    __nv_bfloat162* dst = (__nv_bfloat162*)(g_zb + (size_t)warp * DVEC);
    dst[lane * 2 + 0] = __floats2bfloat162_rn(v.x * scale, v.y * scale);
    dst[lane * 2 + 1] = __floats2bfloat162_rn(v.z * scale, v.w * scale);
}

// one warp per i: exact fp32 positive dot from raw inputs
__global__ void k_pos(const float* __restrict__ zi, const float* __restrict__ zj) {
    int warp = (blockIdx.x * blockDim.x + threadIdx.x) >> 5;
    int lane = threadIdx.x & 31;
    if (warp >= B_ROWS) return;
    float4 a = ((const float4*)(zi + (size_t)warp * DVEC))[lane];
    float4 b = ((const float4*)(zj + (size_t)warp * DVEC))[lane];
    float aa = a.x * a.x + a.y * a.y + a.z * a.z + a.w * a.w;
    float bb = b.x * b.x + b.y * b.y + b.z * b.z + b.w * b.w;
    float ab = a.x * b.x + a.y * b.y + a.z * b.z + a.w * b.w;
    #pragma unroll
    for (int o = 16; o > 0; o >>= 1) {
        aa += __shfl_xor_sync(0xffffffffu, aa, o);
        bb += __shfl_xor_sync(0xffffffffu, bb, o);
        ab += __shfl_xor_sync(0xffffffffu, ab, o);
    }
    if (lane == 0)
        g_pos[warp] = ab / (fmaxf(sqrtf(aa), EPS_N) * fmaxf(sqrtf(bb), EPS_N));
}

// ---------------------------------------------------------------- main HMMA kernel
// CTA tile 128x128, K=128 fully resident. grid (64, 64).
// 8 warps in 2(m) x 4(n); warp tile 64x32 = 4 m16 x 4 n8 tiles, 8 K16 steps.
// Smem: bf16 rows with pitch 272B (17 x 16B, odd mod 8 -> conflict-free ldmatrix).
#define SM_PITCH_B 272
#define TILE_BYTES (128 * SM_PITCH_B)          // 34816
#define SMEM_TOTAL (2 * TILE_BYTES)            // 69632

__global__ void __launch_bounds__(256, 2) k_main() {
    extern __shared__ char sm[];
    char* smA = sm;
    char* smB = sm + TILE_BYTES;

    const int tid  = threadIdx.x;
    const int wid  = tid >> 5;
    const int lane = tid & 31;
    const int row0 = blockIdx.x * 128;
    const int col0 = blockIdx.y * 128;

    // load A & B tiles: 128 rows x 256B each, 16B chunks, coalesced
    const char* zbase = (const char*)g_zb;
    #pragma unroll
    for (int i = 0; i < 8; i++) {
        int idx = tid + i * 256;                 // 0..2047
        int r = idx >> 4, c = idx & 15;
        uint4 va = *(const uint4*)(zbase + (size_t)(row0 + r) * 256 + c * 16);
        *(uint4*)(smA + r * SM_PITCH_B + c * 16) = va;
        uint4 vb = *(const uint4*)(zbase + (size_t)(col0 + r) * 256 + c * 16);
        *(uint4*)(smB + r * SM_PITCH_B + c * 16) = vb;
    }
    __syncthreads();

    const uint32_t aBase = smem_u32(smA);
    const uint32_t bBase = smem_u32(smB);
    const int wm = wid & 1;                      // 0..1
    const int wn = wid >> 1;                     // 0..3
    const int m_off = wm * 64;
    const int n_off = wn * 32;

    // per-lane ldmatrix addressing
    const int arow = lane & 15;                  // A: row within m16 tile
    const int akb  = (lane >> 4) << 4;           // A: +16B for k-quad 1
    const int brow = (lane & 7) + ((lane >> 4) << 3);   // B: row within n16 pair
    const int bkb  = ((lane >> 3) & 1) << 4;     // B: +16B for k-quad 1

    float acc[4][4][4];
    #pragma unroll
    for (int mt = 0; mt < 4; mt++)
        #pragma unroll
        for (int nt = 0; nt < 4; nt++)
            #pragma unroll
            for (int e = 0; e < 4; e++) acc[mt][nt][e] = 0.0f;

    #pragma unroll
    for (int ks = 0; ks < 8; ks++) {
        const int kb = ks * 32;                  // 16 bf16 = 32B per k-step
        uint32_t afr[4][4];
        #pragma unroll
        for (int mt = 0; mt < 4; mt++)
            LDSM4(afr[mt], aBase + (m_off + mt * 16 + arow) * SM_PITCH_B + kb + akb);
        uint32_t bfr[2][4];                      // each x4 covers two n8 tiles
        #pragma unroll
        for (int p = 0; p < 2; p++)
            LDSM4(bfr[p], bBase + (n_off + p * 16 + brow) * SM_PITCH_B + kb + bkb);

        #pragma unroll
        for (int mt = 0; mt < 4; mt++) {
            #pragma unroll
            for (int nt = 0; nt < 4; nt++) {
                uint32_t b0 = bfr[nt >> 1][(nt & 1) * 2 + 0];
                uint32_t b1 = bfr[nt >> 1][(nt & 1) * 2 + 1];
                MMA_BF16(acc[mt][nt], afr[mt], b0, b1);
            }
        }
    }

    // epilogue: exp(2*dot) and per-row sums.
    // c-frag: regs 0,1 -> row (lane/4), cols nt*8+(lane%4)*2+{0,1}; regs 2,3 -> row+8.
    #pragma unroll
    for (int mt = 0; mt < 4; mt++) {
        float s0 = 0.0f, s1 = 0.0f;
        #pragma unroll
        for (int nt = 0; nt < 4; nt++) {
            s0 += exp2d(acc[mt][nt][0]) + exp2d(acc[mt][nt][1]);
            s1 += exp2d(acc[mt][nt][2]) + exp2d(acc[mt][nt][3]);
        }
        s0 += __shfl_xor_sync(0xffffffffu, s0, 1);
        s0 += __shfl_xor_sync(0xffffffffu, s0, 2);
        s1 += __shfl_xor_sync(0xffffffffu, s1, 1);
        s1 += __shfl_xor_sync(0xffffffffu, s1, 2);
        if ((lane & 3) == 0) {
            int r = row0 + m_off + mt * 16 + (lane >> 2);
            atomicAdd(&g_rowsum[r], s0);
            atomicAdd(&g_rowsum[r + 8], s1);
        }
    }
}

// ---------------------------------------------------------------- finalize
__global__ void k_final(float* __restrict__ out) {
    __shared__ float red[256];
    int tid = threadIdx.x;
    float lsum = 0.0f;
    for (int i = tid; i < N_ROWS; i += 256)
        lsum += logf(g_rowsum[i] - E2);
    float psum = 0.0f;
    for (int i = tid; i < B_ROWS; i += 256)
        psum += g_pos[i];
    red[tid] = lsum - 2.0f * INV_T * psum;   // each pos dot appears in 2 rows
    __syncthreads();
    for (int s = 128; s > 0; s >>= 1) {
        if (tid < s) red[tid] += red[tid + s];
        __syncthreads();
    }
    if (tid == 0) out[0] = red[0] / (float)N_ROWS;
}

// ---------------------------------------------------------------- launch
extern "C" void kernel_launch(void* const* d_in, const int* in_sizes, int n_in,
                              void* d_out, int out_size) {
    const float* zi = (const float*)d_in[0];
    const float* zj = (const float*)d_in[1];
    float* out = (float*)d_out;

    cudaFuncSetAttribute(k_main, cudaFuncAttributeMaxDynamicSharedMemorySize, SMEM_TOTAL);

    k_zero<<<(N_ROWS + 255) / 256, 256>>>();
    k_norm<<<N_ROWS / 8, 256>>>(zi, zj);
    k_pos<<<B_ROWS / 8, 256>>>(zi, zj);
    k_main<<<dim3(64, 64), 256, SMEM_TOTAL>>>();
    k_final<<<1, 256>>>(out);
}